// round 11
// baseline (speedup 1.0000x reference)
#include <cuda_runtime.h>
#include <cuda_bf16.h>
#include <cuda_fp16.h>
#include <cstdint>

// ===================== problem constants =====================
#define IN_F   4096
#define OUT_F  11008
#define BM     256
#define BN     32
#define BK     32
#define NC     (IN_F / BK)   // 128 k-chunks
#define THREADS 256

// ===================== smem layout (bytes) ===================
#define OFF_LUT  0                 // 256 f32
#define OFF_STG  1024
#define STG      30720             // per stage: A 20480 | B 2048 | WP 4096 | WF 4096
#define SA       0
#define SB       20480
#define SWP      22528
#define SWF      26624
#define SMEM_BYTES (1024 + 2 * STG)   // 62464

// ===================== device scratch ========================
__device__ __align__(16) __half g_xh[BM * IN_F];   // x converted to fp16 (2 MB)

// ===================== helpers ===============================
static __device__ __forceinline__ uint32_t smem_u32(const void* p) {
    uint32_t a;
    asm("{ .reg .u64 t; cvta.to.shared.u64 t, %1; cvt.u32.u64 %0, t; }"
        : "=r"(a) : "l"(p));
    return a;
}
static __device__ __forceinline__ void cp16(uint32_t d, const void* s) {
    asm volatile("cp.async.cg.shared.global [%0], [%1], 16;" :: "r"(d), "l"(s));
}
#define CP_COMMIT() asm volatile("cp.async.commit_group;" ::: "memory")
#define CP_WAIT0()  asm volatile("cp.async.wait_group 0;" ::: "memory")

static __device__ __forceinline__ void ldsm4(uint32_t* r, uint32_t a) {
    asm volatile("ldmatrix.sync.aligned.m8n8.x4.shared.b16 {%0,%1,%2,%3}, [%4];"
                 : "=r"(r[0]), "=r"(r[1]), "=r"(r[2]), "=r"(r[3]) : "r"(a));
}
static __device__ __forceinline__ void ldsm4t(uint32_t* r, uint32_t a) {
    asm volatile("ldmatrix.sync.aligned.m8n8.x4.trans.shared.b16 {%0,%1,%2,%3}, [%4];"
                 : "=r"(r[0]), "=r"(r[1]), "=r"(r[2]), "=r"(r[3]) : "r"(a));
}
static __device__ __forceinline__ void mma_f16(float* d, const uint32_t* a,
                                               uint32_t b0, uint32_t b1) {
    asm volatile("mma.sync.aligned.m16n8k16.row.col.f32.f16.f16.f32 "
                 "{%0,%1,%2,%3}, {%4,%5,%6,%7}, {%8,%9}, {%0,%1,%2,%3};"
                 : "+f"(d[0]), "+f"(d[1]), "+f"(d[2]), "+f"(d[3])
                 : "r"(a[0]), "r"(a[1]), "r"(a[2]), "r"(a[3]), "r"(b0), "r"(b1));
}
static __device__ __forceinline__ bool is_f32_upcast(const void* p) {
    const uint32_t* w = (const uint32_t*)p;
    return ((w[0] | w[1] | w[2] | w[3]) & 0xFFFFu) == 0u;
}

// ===================== x conversion kernel ===================
__global__ void convert_x(const void* __restrict__ xin) {
    const bool xf32 = is_f32_upcast(xin);
    const int t = blockIdx.x * blockDim.x + threadIdx.x;   // 65536 threads
    #pragma unroll
    for (int h = 0; h < 2; ++h) {
        const int base = t * 16 + h * 8;
        __half o[8];
        if (xf32) {
            const float4* s = (const float4*)((const float*)xin + base);
            const float4 f0 = s[0], f1 = s[1];
            o[0] = __float2half_rn(f0.x); o[1] = __float2half_rn(f0.y);
            o[2] = __float2half_rn(f0.z); o[3] = __float2half_rn(f0.w);
            o[4] = __float2half_rn(f1.x); o[5] = __float2half_rn(f1.y);
            o[6] = __float2half_rn(f1.z); o[7] = __float2half_rn(f1.w);
        } else {
            const __nv_bfloat16* s = (const __nv_bfloat16*)xin + base;
            #pragma unroll
            for (int j = 0; j < 8; ++j) o[j] = __float2half_rn(__bfloat162float(s[j]));
        }
        *(uint4*)(g_xh + base) = *(const uint4*)o;
    }
}

// ===================== main kernel ===========================
extern __shared__ __align__(1024) char smem[];

__global__ void __launch_bounds__(THREADS, 3)
phr_f16_kernel(const void* __restrict__ pA,     // one of W_p / W_f
               const void* __restrict__ pB,     // the other
               const float* __restrict__ lut,
               const void* __restrict__ biasin,
               float* __restrict__ out)
{
    // ---- disambiguate W_p (int32 in [0,256)) vs W_f ----
    const uint32_t* a32 = (const uint32_t*)pA;
    const uint32_t probe = a32[0] | a32[1] | a32[2] | a32[3];
    const int* __restrict__ Wp;
    const void* __restrict__ Wfv;
    if (probe < 256u) { Wp = (const int*)pA; Wfv = pB; }
    else              { Wp = (const int*)pB; Wfv = pA; }
    const bool wf32 = is_f32_upcast(Wfv);
    const bool bf32 = is_f32_upcast(biasin);
    const float* Wf32 = (const float*)Wfv;
    const __nv_bfloat16* Wfbf = (const __nv_bfloat16*)Wfv;

    const int tid  = threadIdx.x;
    const int lane = tid & 31;
    const int wid  = tid >> 5;
    const int n0   = blockIdx.x * BN;
    const uint32_t sb = smem_u32(smem);

    float* lut_s = (float*)(smem + OFF_LUT);
    lut_s[tid] = lut[tid];     // 256 threads exactly
    __syncthreads();

    // ---- dequant coords: 128 tasks (32k x 4 n-chunks of 8) ----
    const int dk = tid >> 2;          // 0..63 (only tid<128 used -> 0..31)
    const int dc = tid & 3;           // n-chunk 0..3

    // ---- MMA coords: 8 warps, warp tile 32m x 32n ----
    const int mw = wid;               // m block of 32 rows
    const int lt = lane >> 3, lr = lane & 7;
    const int g  = lane >> 2, tg = lane & 3;
    const uint32_t a_lane_off = (uint32_t)((mw * 32 + (lt & 1) * 8 + lr) * 80
                                           + (lt >> 1) * 16);

    float acc[2][4][4];
    #pragma unroll
    for (int i = 0; i < 2; ++i)
        #pragma unroll
        for (int j = 0; j < 4; ++j)
            #pragma unroll
            for (int q = 0; q < 4; ++q) acc[i][j][q] = 0.0f;

    auto issue_loads = [&](int c, int st) {
        const int kb = c * BK;
        const uint32_t base = sb + OFF_STG + st * STG;
        // A (fp16 from g_xh): 256 rows x 64B (80B stride) -> 1024 granules, 4/thread
        #pragma unroll
        for (int j = 0; j < 4; ++j) {
            const int t = tid + j * THREADS;
            const int r = t >> 2, q = t & 3;
            cp16(base + SA + r * 80 + q * 16, g_xh + (size_t)r * IN_F + kb + q * 8);
        }
        // WP: 32 k-rows x 32 int32 = 128B rows -> 256 granules, 1/thread
        {
            const int k = tid >> 3, q = tid & 7;
            cp16(base + SWP + k * 128 + q * 16,
                 Wp + (size_t)(kb + k) * OUT_F + n0 + q * 4);
        }
        // WF
        if (wf32) {   // f32: 128B rows, 1/thread
            const int k = tid >> 3, q = tid & 7;
            cp16(base + SWF + k * 128 + q * 16,
                 Wf32 + (size_t)(kb + k) * OUT_F + n0 + q * 4);
        } else if (tid < 128) {  // bf16: 64B rows, 128 granules
            const int k = tid >> 2, q = tid & 3;
            cp16(base + SWF + k * 64 + q * 16,
                 Wfbf + (size_t)(kb + k) * OUT_F + n0 + q * 8);
        }
        CP_COMMIT();
    };

    // B smem: 32k x 32n fp16, rows folded in pairs into 128B lines.
    // k = 2p+e; chunk-of-line = ((e<<2)|dc) ^ (p&7); addr = p*128 + chunk*16.
    auto dequant = [&](int st) {
        if (tid >= 128) return;
        const char* stg = smem + OFF_STG + st * STG;
        const int4 p0 = *(const int4*)(stg + SWP + dk * 128 + dc * 32);
        const int4 p1 = *(const int4*)(stg + SWP + dk * 128 + dc * 32 + 16);
        float wf[8];
        if (wf32) {
            const float4 f0 = *(const float4*)(stg + SWF + dk * 128 + dc * 32);
            const float4 f1 = *(const float4*)(stg + SWF + dk * 128 + dc * 32 + 16);
            wf[0]=f0.x; wf[1]=f0.y; wf[2]=f0.z; wf[3]=f0.w;
            wf[4]=f1.x; wf[5]=f1.y; wf[6]=f1.z; wf[7]=f1.w;
        } else {
            const uint4 u = *(const uint4*)(stg + SWF + dk * 64 + dc * 16);
            wf[0]=__uint_as_float(u.x << 16); wf[1]=__uint_as_float(u.x & 0xFFFF0000u);
            wf[2]=__uint_as_float(u.y << 16); wf[3]=__uint_as_float(u.y & 0xFFFF0000u);
            wf[4]=__uint_as_float(u.z << 16); wf[5]=__uint_as_float(u.z & 0xFFFF0000u);
            wf[6]=__uint_as_float(u.w << 16); wf[7]=__uint_as_float(u.w & 0xFFFF0000u);
        }
        __half o[8];
        o[0] = __float2half_rn(lut_s[p0.x] + wf[0]);
        o[1] = __float2half_rn(lut_s[p0.y] + wf[1]);
        o[2] = __float2half_rn(lut_s[p0.z] + wf[2]);
        o[3] = __float2half_rn(lut_s[p0.w] + wf[3]);
        o[4] = __float2half_rn(lut_s[p1.x] + wf[4]);
        o[5] = __float2half_rn(lut_s[p1.y] + wf[5]);
        o[6] = __float2half_rn(lut_s[p1.z] + wf[6]);
        o[7] = __float2half_rn(lut_s[p1.w] + wf[7]);
        const int p  = dk >> 1, e = dk & 1;
        const int ch = ((e << 2) | dc) ^ (p & 7);
        *(uint4*)(smem + OFF_STG + st * STG + SB + p * 128 + ch * 16) = *(const uint4*)o;
    };

    issue_loads(0, 0);

    for (int c = 0; c < NC; c += 2) {
        #pragma unroll
        for (int half = 0; half < 2; ++half) {
            const int cc = c + half;
            const int st = half;
            CP_WAIT0();
            __syncthreads();
            if (cc + 1 < NC) issue_loads(cc + 1, st ^ 1);
            dequant(st);
            __syncthreads();
            {
                const uint32_t ab = sb + OFF_STG + st * STG + SA + a_lane_off;
                const uint32_t bb = sb + OFF_STG + st * STG + SB;
                #pragma unroll
                for (int s = 0; s < 2; ++s) {
                    uint32_t a[2][4];
                    #pragma unroll
                    for (int mi = 0; mi < 2; ++mi)
                        ldsm4(a[mi], ab + mi * 1280 + s * 32);   // 16 rows x 80B
                    uint32_t bh[8];
                    const int k = s * 16 + (lt & 1) * 8 + lr;
                    const int p = k >> 1, e = k & 1;
                    #pragma unroll
                    for (int pr = 0; pr < 2; ++pr) {
                        const int dcn = pr * 2 + (lt >> 1);       // n-chunk 0..3
                        const int ch  = ((e << 2) | dcn) ^ (p & 7);
                        ldsm4t(bh + pr * 4, bb + (uint32_t)(p * 128 + ch * 16));
                    }
                    #pragma unroll
                    for (int mi = 0; mi < 2; ++mi) {
                        #pragma unroll
                        for (int nj = 0; nj < 4; ++nj) {
                            const int base = (nj >> 1) * 4 + (nj & 1) * 2;
                            mma_f16(acc[mi][nj], a[mi], bh[base], bh[base + 1]);
                        }
                    }
                }
            }
        }
    }

    // ---- epilogue ----
    #pragma unroll
    for (int nj = 0; nj < 4; ++nj) {
        const int n = n0 + nj * 8 + tg * 2;
        float b0, b1;
        if (bf32) {
            b0 = ((const float*)biasin)[n];
            b1 = ((const float*)biasin)[n + 1];
        } else {
            b0 = __bfloat162float(((const __nv_bfloat16*)biasin)[n]);
            b1 = __bfloat162float(((const __nv_bfloat16*)biasin)[n + 1]);
        }
        #pragma unroll
        for (int mi = 0; mi < 2; ++mi) {
            const int m = mw * 32 + mi * 16 + g;
            float2 v0 = make_float2(acc[mi][nj][0] + b0, acc[mi][nj][1] + b1);
            float2 v1 = make_float2(acc[mi][nj][2] + b0, acc[mi][nj][3] + b1);
            *(float2*)(out + (size_t)m * OUT_F + n)       = v0;
            *(float2*)(out + (size_t)(m + 8) * OUT_F + n) = v1;
        }
    }
}

// ===================== launch ================================
extern "C" void kernel_launch(void* const* d_in, const int* in_sizes, int n_in,
                              void* d_out, int out_size)
{
    // Size-keyed input resolution:
    //   x: 1048576, lut: 256, bias: 11008, W_p/W_f: 45088768 each.
    const void* px = nullptr;
    const void* plut = nullptr;
    const void* pbias = nullptr;
    const void* pa = nullptr;
    const void* pb = nullptr;
    for (int i = 0; i < n_in; ++i) {
        const int s = in_sizes[i];
        if (s == 256)          plut = d_in[i];
        else if (s == 11008)   pbias = d_in[i];
        else if (s == 1048576) px = d_in[i];
        else { if (!pa) pa = d_in[i]; else pb = d_in[i]; }
    }

    convert_x<<<256, 256>>>(px);   // 65536 threads x 16 elems

    cudaFuncSetAttribute(phr_f16_kernel,
                         cudaFuncAttributeMaxDynamicSharedMemorySize, SMEM_BYTES);
    phr_f16_kernel<<<OUT_F / BN, THREADS, SMEM_BYTES>>>(
        pa, pb, (const float*)plut, pbias, (float*)d_out);
}

// round 12
// speedup vs baseline: 1.2893x; 1.2893x over previous
#include <cuda_runtime.h>
#include <cuda_bf16.h>
#include <cuda_fp16.h>
#include <cstdint>

// ===================== problem constants =====================
#define IN_F   4096
#define OUT_F  11008
#define BM     256
#define BN     32
#define BK     32
#define NC     (IN_F / BK)   // 128 k-chunks
#define THREADS 256
#define NSTAGE 4

// ===================== smem layout (bytes) ===================
#define OFF_LUT  0                 // 256 f32
#define OFF_STG  1024
// per stage: A 16384 (folded) | B 2048 | WP 4096 | WF 4096
#define SA       0
#define SB       16384
#define SWP      18432
#define SWF      22528
#define STG      26624
#define SMEM_BYTES (1024 + NSTAGE * STG)   // 107520 (x2 CTAs = 215040 <= 228KB)

// ===================== device scratch ========================
__device__ __align__(16) __half g_xh[BM * IN_F];   // x as fp16 (2 MB, L2-resident)

// ===================== helpers ===============================
static __device__ __forceinline__ uint32_t smem_u32(const void* p) {
    uint32_t a;
    asm("{ .reg .u64 t; cvta.to.shared.u64 t, %1; cvt.u32.u64 %0, t; }"
        : "=r"(a) : "l"(p));
    return a;
}
static __device__ __forceinline__ void cp16(uint32_t d, const void* s) {
    asm volatile("cp.async.cg.shared.global [%0], [%1], 16;" :: "r"(d), "l"(s));
}
#define CP_COMMIT() asm volatile("cp.async.commit_group;" ::: "memory")
#define CP_WAIT2()  asm volatile("cp.async.wait_group 2;" ::: "memory")
#define CP_WAIT0()  asm volatile("cp.async.wait_group 0;" ::: "memory")

static __device__ __forceinline__ void ldsm4(uint32_t* r, uint32_t a) {
    asm volatile("ldmatrix.sync.aligned.m8n8.x4.shared.b16 {%0,%1,%2,%3}, [%4];"
                 : "=r"(r[0]), "=r"(r[1]), "=r"(r[2]), "=r"(r[3]) : "r"(a));
}
static __device__ __forceinline__ void ldsm4t(uint32_t* r, uint32_t a) {
    asm volatile("ldmatrix.sync.aligned.m8n8.x4.trans.shared.b16 {%0,%1,%2,%3}, [%4];"
                 : "=r"(r[0]), "=r"(r[1]), "=r"(r[2]), "=r"(r[3]) : "r"(a));
}
static __device__ __forceinline__ void mma_f16(float* d, const uint32_t* a,
                                               uint32_t b0, uint32_t b1) {
    asm volatile("mma.sync.aligned.m16n8k16.row.col.f32.f16.f16.f32 "
                 "{%0,%1,%2,%3}, {%4,%5,%6,%7}, {%8,%9}, {%0,%1,%2,%3};"
                 : "+f"(d[0]), "+f"(d[1]), "+f"(d[2]), "+f"(d[3])
                 : "r"(a[0]), "r"(a[1]), "r"(a[2]), "r"(a[3]), "r"(b0), "r"(b1));
}
static __device__ __forceinline__ bool is_f32_upcast(const void* p) {
    const uint32_t* w = (const uint32_t*)p;
    return ((w[0] | w[1] | w[2] | w[3]) & 0xFFFFu) == 0u;
}

// ===================== x conversion kernel ===================
__global__ void convert_x(const void* __restrict__ xin) {
    const bool xf32 = is_f32_upcast(xin);
    const int t = blockIdx.x * blockDim.x + threadIdx.x;   // 65536 threads
    #pragma unroll
    for (int h = 0; h < 2; ++h) {
        const int base = t * 16 + h * 8;
        __half o[8];
        if (xf32) {
            const float4* s = (const float4*)((const float*)xin + base);
            const float4 f0 = s[0], f1 = s[1];
            o[0] = __float2half_rn(f0.x); o[1] = __float2half_rn(f0.y);
            o[2] = __float2half_rn(f0.z); o[3] = __float2half_rn(f0.w);
            o[4] = __float2half_rn(f1.x); o[5] = __float2half_rn(f1.y);
            o[6] = __float2half_rn(f1.z); o[7] = __float2half_rn(f1.w);
        } else {
            const __nv_bfloat16* s = (const __nv_bfloat16*)xin + base;
            #pragma unroll
            for (int j = 0; j < 8; ++j) o[j] = __float2half_rn(__bfloat162float(s[j]));
        }
        *(uint4*)(g_xh + base) = *(const uint4*)o;
    }
}

// ===================== main kernel ===========================
extern __shared__ __align__(1024) char smem[];

__global__ void __launch_bounds__(THREADS, 2)
phr_f16_kernel(const void* __restrict__ pA,     // one of W_p / W_f
               const void* __restrict__ pB,     // the other
               const float* __restrict__ lut,
               const void* __restrict__ biasin,
               float* __restrict__ out)
{
    // ---- disambiguate W_p (int32 in [0,256)) vs W_f ----
    const uint32_t* a32 = (const uint32_t*)pA;
    const uint32_t probe = a32[0] | a32[1] | a32[2] | a32[3];
    const int* __restrict__ Wp;
    const void* __restrict__ Wfv;
    if (probe < 256u) { Wp = (const int*)pA; Wfv = pB; }
    else              { Wp = (const int*)pB; Wfv = pA; }
    const bool wf32 = is_f32_upcast(Wfv);
    const bool bf32 = is_f32_upcast(biasin);
    const float* Wf32 = (const float*)Wfv;
    const __nv_bfloat16* Wfbf = (const __nv_bfloat16*)Wfv;

    const int tid  = threadIdx.x;
    const int lane = tid & 31;
    const int wid  = tid >> 5;
    const int n0   = blockIdx.x * BN;
    const uint32_t sb = smem_u32(smem);

    float* lut_s = (float*)(smem + OFF_LUT);
    lut_s[tid] = lut[tid];     // 256 threads exactly
    __syncthreads();

    // ---- dequant coords: 256 tasks (32k x 8 n-quads of 4) ----
    const int dk = tid >> 3;          // 0..31
    const int dq = tid & 7;           // n-quad: n = dq*4..dq*4+3

    // ---- MMA coords: 8 warps, warp tile 32m x 32n ----
    const int mw = wid;
    const int lt = lane >> 3, lr = lane & 7;
    const int g  = lane >> 2, tg = lane & 3;

    float acc[2][4][4];
    #pragma unroll
    for (int i = 0; i < 2; ++i)
        #pragma unroll
        for (int j = 0; j < 4; ++j)
            #pragma unroll
            for (int q = 0; q < 4; ++q) acc[i][j][q] = 0.0f;

    // A smem: rows of 64B folded 2-per-128B line; 16B chunk swizzle:
    //   line = r>>1, e = r&1, ch = ((e<<2)|q) ^ (line&7)
    auto issue_loads = [&](int c, int st) {
        const int kb = c * BK;
        const uint32_t base = sb + OFF_STG + st * STG;
        // A: 1024 granules (256 rows x 4 chunks), 4/thread
        #pragma unroll
        for (int j = 0; j < 4; ++j) {
            const int t = tid + j * THREADS;
            const int r = t >> 2, q = t & 3;
            const int line = r >> 1, e = r & 1;
            const int ch = ((e << 2) | q) ^ (line & 7);
            cp16(base + SA + line * 128 + ch * 16,
                 g_xh + (size_t)r * IN_F + kb + q * 8);
        }
        // WP: 32 x 32 int32 = 128B rows, 1 granule/thread
        {
            const int k = tid >> 3, q = tid & 7;
            cp16(base + SWP + k * 128 + q * 16,
                 Wp + (size_t)(kb + k) * OUT_F + n0 + q * 4);
        }
        // WF
        if (wf32) {
            const int k = tid >> 3, q = tid & 7;
            cp16(base + SWF + k * 128 + q * 16,
                 Wf32 + (size_t)(kb + k) * OUT_F + n0 + q * 4);
        } else if (tid < 128) {
            const int k = tid >> 2, q = tid & 3;
            cp16(base + SWF + k * 64 + q * 16,
                 Wfbf + (size_t)(kb + k) * OUT_F + n0 + q * 8);
        }
        CP_COMMIT();
    };

    // B smem: 32k x 32n fp16, k-rows folded 2-per-128B line.
    //   k = 2p+e; 16B chunk ch = ((e<<2)|c16) ^ (p&7); this thread writes 8B.
    auto dequant = [&](int st) {
        const char* stg = smem + OFF_STG + st * STG;
        const int4 p0 = *(const int4*)(stg + SWP + dk * 128 + dq * 16);
        float wf[4];
        if (wf32) {
            const float4 f0 = *(const float4*)(stg + SWF + dk * 128 + dq * 16);
            wf[0] = f0.x; wf[1] = f0.y; wf[2] = f0.z; wf[3] = f0.w;
        } else {
            const uint2 u = *(const uint2*)(stg + SWF + dk * 64 + dq * 8);
            wf[0] = __uint_as_float(u.x << 16);
            wf[1] = __uint_as_float(u.x & 0xFFFF0000u);
            wf[2] = __uint_as_float(u.y << 16);
            wf[3] = __uint_as_float(u.y & 0xFFFF0000u);
        }
        __half o[4];
        o[0] = __float2half_rn(lut_s[p0.x] + wf[0]);
        o[1] = __float2half_rn(lut_s[p0.y] + wf[1]);
        o[2] = __float2half_rn(lut_s[p0.z] + wf[2]);
        o[3] = __float2half_rn(lut_s[p0.w] + wf[3]);
        const int p  = dk >> 1, e = dk & 1;
        const int ch = ((e << 2) | (dq >> 1)) ^ (p & 7);
        *(uint2*)(smem + OFF_STG + st * STG + SB + p * 128 + ch * 16 + (dq & 1) * 8)
            = *(const uint2*)o;
    };

    // ---- prologue: fill 3 stages ----
    issue_loads(0, 0);
    issue_loads(1, 1);
    issue_loads(2, 2);

    for (int cc = 0; cc < NC; ++cc) {
        const int st = cc & (NSTAGE - 1);
        CP_WAIT2();                 // group cc has landed (<=2 newer pending)
        __syncthreads();            // all warps done with MMA(cc-1) smem reads
        dequant(st);
        if (cc + 3 < NC) issue_loads(cc + 3, (cc + 3) & (NSTAGE - 1));
        __syncthreads();            // B(st) visible
        {
            const uint32_t ab = sb + OFF_STG + st * STG + SA;
            const uint32_t bb = sb + OFF_STG + st * STG + SB;
            #pragma unroll
            for (int s = 0; s < 2; ++s) {
                uint32_t a[2][4];
                #pragma unroll
                for (int mi = 0; mi < 2; ++mi) {
                    const int r = mw * 32 + mi * 16 + (lt & 1) * 8 + lr;
                    const int q = s * 2 + (lt >> 1);
                    const int line = r >> 1, e = r & 1;
                    const int ch = ((e << 2) | q) ^ (line & 7);
                    ldsm4(a[mi], ab + (uint32_t)(line * 128 + ch * 16));
                }
                uint32_t bh[8];
                const int k = s * 16 + (lt & 1) * 8 + lr;
                const int p = k >> 1, e = k & 1;
                #pragma unroll
                for (int pr = 0; pr < 2; ++pr) {
                    const int c16 = pr * 2 + (lt >> 1);   // n 16B-chunk 0..3
                    const int ch  = ((e << 2) | c16) ^ (p & 7);
                    ldsm4t(bh + pr * 4, bb + (uint32_t)(p * 128 + ch * 16));
                }
                #pragma unroll
                for (int mi = 0; mi < 2; ++mi) {
                    #pragma unroll
                    for (int nj = 0; nj < 4; ++nj) {
                        const int base = (nj >> 1) * 4 + (nj & 1) * 2;
                        mma_f16(acc[mi][nj], a[mi], bh[base], bh[base + 1]);
                    }
                }
            }
        }
    }

    // ---- epilogue ----
    #pragma unroll
    for (int nj = 0; nj < 4; ++nj) {
        const int n = n0 + nj * 8 + tg * 2;
        float b0, b1;
        if (bf32) {
            b0 = ((const float*)biasin)[n];
            b1 = ((const float*)biasin)[n + 1];
        } else {
            b0 = __bfloat162float(((const __nv_bfloat16*)biasin)[n]);
            b1 = __bfloat162float(((const __nv_bfloat16*)biasin)[n + 1]);
        }
        #pragma unroll
        for (int mi = 0; mi < 2; ++mi) {
            const int m = mw * 32 + mi * 16 + g;
            float2 v0 = make_float2(acc[mi][nj][0] + b0, acc[mi][nj][1] + b1);
            float2 v1 = make_float2(acc[mi][nj][2] + b0, acc[mi][nj][3] + b1);
            *(float2*)(out + (size_t)m * OUT_F + n)       = v0;
            *(float2*)(out + (size_t)(m + 8) * OUT_F + n) = v1;
        }
    }
}

// ===================== launch ================================
extern "C" void kernel_launch(void* const* d_in, const int* in_sizes, int n_in,
                              void* d_out, int out_size)
{
    // Size-keyed input resolution:
    //   x: 1048576, lut: 256, bias: 11008, W_p/W_f: 45088768 each.
    const void* px = nullptr;
    const void* plut = nullptr;
    const void* pbias = nullptr;
    const void* pa = nullptr;
    const void* pb = nullptr;
    for (int i = 0; i < n_in; ++i) {
        const int s = in_sizes[i];
        if (s == 256)          plut = d_in[i];
        else if (s == 11008)   pbias = d_in[i];
        else if (s == 1048576) px = d_in[i];
        else { if (!pa) pa = d_in[i]; else pb = d_in[i]; }
    }

    convert_x<<<256, 256>>>(px);

    cudaFuncSetAttribute(phr_f16_kernel,
                         cudaFuncAttributeMaxDynamicSharedMemorySize, SMEM_BYTES);
    phr_f16_kernel<<<OUT_F / BN, THREADS, SMEM_BYTES>>>(
        pa, pb, (const float*)plut, pbias, (float*)d_out);
}